// round 1
// baseline (speedup 1.0000x reference)
#include <cuda_runtime.h>
#include <cuda_bf16.h>
#include <cstdint>

// Problem shape (fixed by the dataset): predict (8,19,512,1024) f32, target (8,512,1024)
#define HW_BITS 19
#define HW (1 << HW_BITS)          // 512*1024 = 524288
#define NCLS 19
#define NIMG 8
#define TOTAL_PX (NIMG * HW)       // 4194304
#define PX_PER_THREAD 4
#define NTHR 256
#define NBLK (TOTAL_PX / (PX_PER_THREAD * NTHR))  // 4096

#define TH1 0.8f
#define TH2 0.5f
#define IGNORE_LBL 255

// Per-block partials: [component][block], component = {w_easy, wn_easy, w_mid, wn_mid, w_hard, wn_hard}
__device__ float g_part[6 * NBLK];
__device__ int g_is_i64;

// ---------------------------------------------------------------------------
// Detect whether target buffer is int64 or int32.
// View buffer as int32. If data is int64 little-endian with values in [0,19),
// every odd int32 slot (the high half) is 0. If data is int32 labels, odd
// slots are labels in [0,19): P(64 consecutive odd slots all zero) = (1/19)^64.
// ---------------------------------------------------------------------------
__global__ void detect_kernel(const int* __restrict__ t32) {
    int lane = threadIdx.x;                     // 0..31
    int v = t32[2 * lane + 1] | t32[128 + 2 * lane + 1];   // 64 odd slots total
    unsigned any = __ballot_sync(0xffffffffu, v != 0);
    if (lane == 0) g_is_i64 = (any == 0) ? 1 : 0;
}

// ---------------------------------------------------------------------------
// Main streaming kernel: one pass over all logits.
// Each thread handles 4 consecutive pixels (float4 per channel).
// ---------------------------------------------------------------------------
__global__ __launch_bounds__(NTHR) void ohem_kernel(
    const float* __restrict__ predict,
    const void*  __restrict__ target,
    const float* __restrict__ cw)
{
    const int tid = blockIdx.x * NTHR + threadIdx.x;
    const long g = (long)tid * PX_PER_THREAD;       // global pixel index (always < TOTAL_PX)

    const int n = (int)(g >> HW_BITS);
    const int p = (int)(g & (HW - 1));

    // Base float4 pointer for this pixel group in image n; channel stride = HW floats = HW/4 float4
    const float4* base =
        reinterpret_cast<const float4*>(predict) + (((long)n * NCLS) << (HW_BITS - 2)) + (p >> 2);

    int t[4];
    if (g_is_i64) {
        const longlong2* tp = reinterpret_cast<const longlong2*>(
            (const char*)target + (size_t)g * 8);
        longlong2 a = __ldg(tp);
        longlong2 b = __ldg(tp + 1);
        t[0] = (int)a.x; t[1] = (int)a.y; t[2] = (int)b.x; t[3] = (int)b.y;
    } else {
        int4 a = __ldg(reinterpret_cast<const int4*>((const char*)target + (size_t)g * 4));
        t[0] = a.x; t[1] = a.y; t[2] = a.z; t[3] = a.w;
    }

    // Streaming softmax-denominator (no max subtraction needed: |logit| <~ 25, exp fits fp32).
    float4 s  = make_float4(0.f, 0.f, 0.f, 0.f);
    float4 xt = make_float4(0.f, 0.f, 0.f, 0.f);

    #pragma unroll
    for (int c = 0; c < NCLS; c++) {
        float4 x = __ldg(base + ((long)c << (HW_BITS - 2)));
        s.x += __expf(x.x); if (t[0] == c) xt.x = x.x;
        s.y += __expf(x.y); if (t[1] == c) xt.y = x.y;
        s.z += __expf(x.z); if (t[2] == c) xt.z = x.z;
        s.w += __expf(x.w); if (t[3] == c) xt.w = x.w;
    }

    float acc[6] = {0.f, 0.f, 0.f, 0.f, 0.f, 0.f};
    float xs[4] = {xt.x, xt.y, xt.z, xt.w};
    float ss[4] = {s.x,  s.y,  s.z,  s.w};

    #pragma unroll
    for (int k = 0; k < PX_PER_THREAD; k++) {
        int tk = t[k];
        if (tk >= 0 && tk < NCLS) {            // excludes IGNORE=255 and garbage
            float nll   = __logf(ss[k]) - xs[k];
            float ptrue = __expf(-nll);        // = softmax prob of true class
            float w     = __ldg(cw + tk);
            int b = (ptrue >= TH1) ? 0 : ((ptrue >= TH2) ? 1 : 2);
            acc[2 * b]     += w;
            acc[2 * b + 1] += w * nll;
        }
    }

    // --- block reduction: warp shuffle, then cross-warp via shared ---
    #pragma unroll
    for (int i = 0; i < 6; i++) {
        #pragma unroll
        for (int off = 16; off > 0; off >>= 1)
            acc[i] += __shfl_down_sync(0xffffffffu, acc[i], off);
    }

    __shared__ float sm[NTHR / 32][6];
    const int wid  = threadIdx.x >> 5;
    const int lane = threadIdx.x & 31;
    if (lane == 0) {
        #pragma unroll
        for (int i = 0; i < 6; i++) sm[wid][i] = acc[i];
    }
    __syncthreads();
    if (threadIdx.x < 6) {
        float v = 0.f;
        #pragma unroll
        for (int wi = 0; wi < NTHR / 32; wi++) v += sm[wi][threadIdx.x];
        g_part[threadIdx.x * NBLK + blockIdx.x] = v;
    }
}

// ---------------------------------------------------------------------------
// Finalize: reduce 4096 partials per component in double, emit scalar loss.
// ---------------------------------------------------------------------------
__global__ __launch_bounds__(NTHR) void finalize_kernel(float* __restrict__ out) {
    __shared__ double smem[NTHR];
    double comp[6];

    for (int i = 0; i < 6; i++) {
        double v = 0.0;
        for (int b = threadIdx.x; b < NBLK; b += NTHR)
            v += (double)g_part[i * NBLK + b];
        smem[threadIdx.x] = v;
        __syncthreads();
        for (int off = NTHR / 2; off > 0; off >>= 1) {
            if (threadIdx.x < off) smem[threadIdx.x] += smem[threadIdx.x + off];
            __syncthreads();
        }
        comp[i] = smem[0];
        __syncthreads();
    }

    if (threadIdx.x == 0) {
        double loss = 0.0;
        #pragma unroll
        for (int b = 0; b < 3; b++) {
            double den = comp[2 * b];
            if (den < 1e-12) den = 1e-12;
            loss += comp[2 * b + 1] / den;
        }
        out[0] = (float)loss;
    }
}

// ---------------------------------------------------------------------------
extern "C" void kernel_launch(void* const* d_in, const int* in_sizes, int n_in,
                              void* d_out, int out_size) {
    const float* predict = (const float*)d_in[0];
    const void*  target  = d_in[1];
    const float* cw      = (const float*)d_in[2];

    detect_kernel<<<1, 32>>>((const int*)target);
    ohem_kernel<<<NBLK, NTHR>>>(predict, target, cw);
    finalize_kernel<<<1, NTHR>>>((float*)d_out);
}